// round 2
// baseline (speedup 1.0000x reference)
#include <cuda_runtime.h>
#include <cuda_fp16.h>
#include <cstdint>

#define BZ 32
#define CH 64
#define HH 128
#define WW 128
#define TILE_H 8
#define TILE_W 32
#define MP_STRIDE 264   // words per c2-plane (256 px + 8 pad): conflict-free stores & mma reads
#define WP_STRIDE 33    // words per o-row of packed weights
#define DS 132          // floats per o-row of staged D (128 px + 4 pad, float4-aligned)

// dynamic smem layout (bytes):
//   Mp    uint32_t[32*264]   @ 0        (33792)  fp16x2 box means, [c/2][pixel]
//   Wp    uint32_t[64*33]    @ 33792    (8448)   fp16x2 weights,   [o][c/2]
//   BiasS float[64]          @ 42240    (256)
//   Dsm   float[64*132]      @ 42496    (33792)  staged conv output, [o][px in half]
#define SMEM_BYTES (42496 + 33792)

__global__ __launch_bounds__(256, 3)
void denoise_fused_kernel(const float* __restrict__ x,
                          const float* __restrict__ conv_w,
                          const float* __restrict__ conv_b,
                          float* __restrict__ out) {
    extern __shared__ unsigned char smraw[];
    uint32_t* Mp    = reinterpret_cast<uint32_t*>(smraw);
    uint32_t* Wp    = reinterpret_cast<uint32_t*>(smraw + 33792);
    float*    BiasS = reinterpret_cast<float*>(smraw + 42240);
    float*    Dsm   = reinterpret_cast<float*>(smraw + 42496);

    const int tid  = threadIdx.x;
    const int warp = tid >> 5;
    const int lane = tid & 31;

    const int b  = blockIdx.z;
    const int h0 = blockIdx.y * TILE_H;
    const int w0 = blockIdx.x * TILE_W;

    // ---------- phase 0: stage weights (fp16x2) + bias ----------
    for (int i = tid; i < 64 * 32; i += 256) {
        const int o = i >> 5, c2 = i & 31;
        const float2 wv = reinterpret_cast<const float2*>(conv_w)[o * 32 + c2];
        __half2 pk = __floats2half2_rn(wv.x, wv.y);
        Wp[o * WP_STRIDE + c2] = *reinterpret_cast<uint32_t*>(&pk);
    }
    if (tid < 64) BiasS[tid] = conv_b[tid];

    // ---------- phase 1: edge-clipped 3x3 box mean -> fp16x2 smem ----------
    const float* xb = x + (size_t)b * CH * HH * WW;
    const int   w    = w0 + lane;
    const float invw = (w == 0 || w == WW - 1) ? 0.5f : (1.0f / 3.0f);

    for (int chunk = 0; chunk < 4; chunk++) {
        const int ca = chunk * 16 + warp * 2;
        const float* pa  = xb + ca * (HH * WW);
        const float* pb2 = pa + (HH * WW);
        float hsA[10], hsB[10];
        #pragma unroll
        for (int i = 0; i < 10; i++) {
            const int r = h0 - 1 + i;
            const bool rin = (r >= 0) && (r < HH);
            float va = 0.f, vb = 0.f;
            if (rin) { va = pa[r * WW + w]; vb = pb2[r * WW + w]; }
            float la = __shfl_up_sync(0xffffffffu, va, 1);
            float lb = __shfl_up_sync(0xffffffffu, vb, 1);
            float ra = __shfl_down_sync(0xffffffffu, va, 1);
            float rb = __shfl_down_sync(0xffffffffu, vb, 1);
            if (lane == 0) {
                la = (rin && w0 > 0) ? pa[r * WW + w0 - 1]  : 0.f;
                lb = (rin && w0 > 0) ? pb2[r * WW + w0 - 1] : 0.f;
            }
            if (lane == 31) {
                ra = (rin && (w0 + TILE_W) < WW) ? pa[r * WW + w0 + TILE_W]  : 0.f;
                rb = (rin && (w0 + TILE_W) < WW) ? pb2[r * WW + w0 + TILE_W] : 0.f;
            }
            hsA[i] = la + va + ra;
            hsB[i] = lb + vb + rb;
        }
        #pragma unroll
        for (int ro = 0; ro < TILE_H; ro++) {
            const int h = h0 + ro;
            const float invh = (h == 0 || h == HH - 1) ? 0.5f : (1.0f / 3.0f);
            const float s = invh * invw;
            const float ma = (hsA[ro] + hsA[ro + 1] + hsA[ro + 2]) * s;
            const float mb = (hsB[ro] + hsB[ro + 1] + hsB[ro + 2]) * s;
            __half2 pk = __floats2half2_rn(ma, mb);
            Mp[(ca >> 1) * MP_STRIDE + ro * 32 + lane] =
                *reinterpret_cast<uint32_t*>(&pk);
        }
    }
    __syncthreads();

    // ---------- phase 2: channel GEMM on tensor pipe, per pixel-half ----------
    // D[o, p] = sum_c W[o,c] * mean[p,c];  per half: M=64 (o), N=128 (px), K=64
    // warp -> m-tile (warp>>1)*16, n-subtile (warp&1)*64
    const int o0   = (warp >> 1) * 16;
    const int nsub = (warp & 1) * 64;
    const int lq = lane >> 2;   // 0..7
    const int lr = lane & 3;    // 0..3

    uint32_t a[4][4];
    #pragma unroll
    for (int kk = 0; kk < 4; kk++) {
        a[kk][0] = Wp[(o0 + lq)     * WP_STRIDE + kk * 8 + lr];
        a[kk][1] = Wp[(o0 + 8 + lq) * WP_STRIDE + kk * 8 + lr];
        a[kk][2] = Wp[(o0 + lq)     * WP_STRIDE + kk * 8 + 4 + lr];
        a[kk][3] = Wp[(o0 + 8 + lq) * WP_STRIDE + kk * 8 + 4 + lr];
    }
    const int oA = o0 + lq, oB = oA + 8;
    const size_t planeBase = (size_t)b * CH * (HH * WW);

    #pragma unroll 1
    for (int half = 0; half < 2; half++) {
        const int pbase = half * 128;

        #pragma unroll
        for (int nt = 0; nt < 8; nt++) {
            const int n0 = nsub + nt * 8;           // local pixel within half
            float acc0 = 0.f, acc1 = 0.f, acc2 = 0.f, acc3 = 0.f;
            #pragma unroll
            for (int kk = 0; kk < 4; kk++) {
                const uint32_t b0 = Mp[(kk * 8 + lr)     * MP_STRIDE + pbase + n0 + lq];
                const uint32_t b1 = Mp[(kk * 8 + 4 + lr) * MP_STRIDE + pbase + n0 + lq];
                asm volatile(
                    "mma.sync.aligned.m16n8k16.row.col.f32.f16.f16.f32 "
                    "{%0,%1,%2,%3}, {%4,%5,%6,%7}, {%8,%9}, {%0,%1,%2,%3};\n"
                    : "+f"(acc0), "+f"(acc1), "+f"(acc2), "+f"(acc3)
                    : "r"(a[kk][0]), "r"(a[kk][1]), "r"(a[kk][2]), "r"(a[kk][3]),
                      "r"(b0), "r"(b1));
            }
            const int p0 = n0 + lr * 2;
            *reinterpret_cast<float2*>(&Dsm[oA * DS + p0]) = make_float2(acc0, acc1);
            *reinterpret_cast<float2*>(&Dsm[oB * DS + p0]) = make_float2(acc2, acc3);
        }
        __syncthreads();

        // cooperative coalesced epilogue: out = x + bias + D  (float4)
        #pragma unroll
        for (int i = 0; i < 8; i++) {
            const int f = i * 256 + tid;    // float4 index, 2048 per half
            const int o = f >> 5;           // 0..63
            const int q = f & 31;           // float4 within 128 px
            const int p = pbase + q * 4;    // pixel in tile
            const int hh = h0 + (p >> 5);
            const int wc = w0 + (p & 31);
            const size_t off = planeBase + (size_t)o * (HH * WW) + hh * WW + wc;
            const float4 xv = *reinterpret_cast<const float4*>(x + off);
            const float4 dv = *reinterpret_cast<const float4*>(&Dsm[o * DS + q * 4]);
            const float bo = BiasS[o];
            float4 ov;
            ov.x = xv.x + bo + dv.x;
            ov.y = xv.y + bo + dv.y;
            ov.z = xv.z + bo + dv.z;
            ov.w = xv.w + bo + dv.w;
            *reinterpret_cast<float4*>(out + off) = ov;
        }
        __syncthreads();   // Dsm reuse fence for next half
    }
}

extern "C" void kernel_launch(void* const* d_in, const int* in_sizes, int n_in,
                              void* d_out, int out_size) {
    const float* x      = (const float*)d_in[0];
    const float* conv_w = (const float*)d_in[1];
    const float* conv_b = (const float*)d_in[2];
    float* out = (float*)d_out;
    cudaFuncSetAttribute(denoise_fused_kernel,
                         cudaFuncAttributeMaxDynamicSharedMemorySize, SMEM_BYTES);
    dim3 grid(WW / TILE_W, HH / TILE_H, BZ);   // 4 x 16 x 32 = 2048 CTAs
    denoise_fused_kernel<<<grid, 256, SMEM_BYTES>>>(x, conv_w, conv_b, out);
}